// round 7
// baseline (speedup 1.0000x reference)
#include <cuda_runtime.h>
#include <cstdint>

// ---------------------------------------------------------------------------
// GRUSeq2Seq on GB300 (sm_103a) — round 6
// 147 persistent CTAs x 14 batch rows (7 f32x2 pairs). NT=768:
//   tid = q*192 + jc   (q = warp-uniform K-quarter, jc lane-consecutive)
// Thread computes 2 gate columns (jc, jc+192) x 7 row-pairs over its
// K-quarter. Zero weight-load redundancy; 6 warps/SMSP hide LDG/LDS latency.
// K-partials in 4 smem buffers, combined in the gates phase. fp32 via
// fma.rn.f32x2.
// ---------------------------------------------------------------------------

#define HID   128
#define NFEAT 16
#define TIN   336
#define TOUT  168
#define BATCH 2048
#define NP    7
#define NROW  (2*NP)
#define NT    768
#define NBLK  147
#define GBUF  2688        // ull per partial gate buffer (NP*384)

typedef unsigned long long ull;

// ------------------------- transposed weight scratch -----------------------
__device__ float g_We0i[NFEAT * 384];  // float4 layout [k/4][384][4]
__device__ float g_We0h[HID * 384];
__device__ float g_We1i[HID * 384];
__device__ float g_We1h[HID * 384];
__device__ float g_Wd0h[HID * 384];
__device__ float g_Wd1i[HID * 384];
__device__ float g_Wd1h[HID * 384];
__device__ float g_Wfc1[HID * 64];     // pair layout [k/2][64][2]

// ------------------------- packed f32x2 helpers ----------------------------
__device__ __forceinline__ ull pk2(float lo, float hi) {
    ull r;
    asm("mov.b64 %0, {%1, %2};" : "=l"(r) : "f"(lo), "f"(hi));
    return r;
}
__device__ __forceinline__ float2 upk(ull v) {
    float a, b;
    asm("mov.b64 {%0, %1}, %2;" : "=f"(a), "=f"(b) : "l"(v));
    return make_float2(a, b);
}
__device__ __forceinline__ ull ffma2(ull a, ull b, ull c) {
    ull d;
    asm("fma.rn.f32x2 %0, %1, %2, %3;" : "=l"(d) : "l"(a), "l"(b), "l"(c));
    return d;
}
__device__ __forceinline__ ull add2(ull a, ull b) {
    ull d;
    asm("add.rn.f32x2 %0, %1, %2;" : "=l"(d) : "l"(a), "l"(b));
    return d;
}

__device__ __forceinline__ float sigmf(float v) {
    return 1.0f / (1.0f + __expf(-v));
}
__device__ __forceinline__ float tanh_f(float v) {
    float e = __expf(-2.0f * fabsf(v));
    float t = (1.0f - e) / (1.0f + e);
    return copysignf(t, v);
}

// ------------------------- quarter-K dual-column GEMM -----------------------
// Thread computes columns jc, jc+192 for all NP row-pairs over K-quarter q.
// Partial sums stored to dst (the q-th partial buffer). h reads are
// warp-uniform (q, k4, p identical across lanes) -> LDS broadcast.
template <int K>
__device__ __forceinline__ void gemm2q(const float* __restrict__ Wf,
                                       const ull* __restrict__ hs,
                                       ull* __restrict__ dst,
                                       int jc, int q) {
    const float4* W4 = reinterpret_cast<const float4*>(Wf);
    constexpr int QG = K / 16;          // float4 groups per K-quarter
    const int k4b = q * QG;
    ull a0[NP], a1[NP];
#pragma unroll
    for (int p = 0; p < NP; p++) { a0[p] = 0ull; a1[p] = 0ull; }

#pragma unroll 2
    for (int i = 0; i < QG; i++) {
        const int k4 = k4b + i;
        const float4* wrow = &W4[k4 * 384 + jc];
        float4 wA = __ldg(wrow);
        float4 wB = __ldg(wrow + 192);
        ull wa0 = pk2(wA.x, wA.x), wa1 = pk2(wA.y, wA.y);
        ull wa2 = pk2(wA.z, wA.z), wa3 = pk2(wA.w, wA.w);
        ull wb0 = pk2(wB.x, wB.x), wb1 = pk2(wB.y, wB.y);
        ull wb2 = pk2(wB.z, wB.z), wb3 = pk2(wB.w, wB.w);
#pragma unroll
        for (int p = 0; p < NP; p++) {
            const ull* hp = &hs[p * K + 4 * k4];
            ulonglong2 h01 = *reinterpret_cast<const ulonglong2*>(hp);
            ulonglong2 h23 = *reinterpret_cast<const ulonglong2*>(hp + 2);
            a0[p] = ffma2(h01.x, wa0, a0[p]);
            a1[p] = ffma2(h01.x, wb0, a1[p]);
            a0[p] = ffma2(h01.y, wa1, a0[p]);
            a1[p] = ffma2(h01.y, wb1, a1[p]);
            a0[p] = ffma2(h23.x, wa2, a0[p]);
            a1[p] = ffma2(h23.x, wb2, a1[p]);
            a0[p] = ffma2(h23.y, wa3, a0[p]);
            a1[p] = ffma2(h23.y, wb3, a1[p]);
        }
    }
#pragma unroll
    for (int p = 0; p < NP; p++) {
        dst[p * 384 + jc]       = a0[p];
        dst[p * 384 + jc + 192] = a1[p];
    }
}

// ------------------------- GRU gate phase (4-way combine) -------------------
__device__ __forceinline__ void gates4(ull* hs,
                                       const ull* giq, const ull* ghq,
                                       const float* bih, const float* bhh,
                                       int tid) {
    for (int i = tid; i < HID * NP; i += NT) {
        int u = i & (HID - 1);
        int p = i >> 7;
        int b0 = p * 384 + u;
        ull sir = 0, siz = 0, sin = 0, shr = 0, shz = 0, shn = 0;
#pragma unroll
        for (int s = 0; s < 4; s++) {
            const ull* gi = giq + s * GBUF;
            const ull* gh = ghq + s * GBUF;
            sir = add2(sir, gi[b0]);
            siz = add2(siz, gi[b0 + HID]);
            sin = add2(sin, gi[b0 + 2 * HID]);
            shr = add2(shr, gh[b0]);
            shz = add2(shz, gh[b0 + HID]);
            shn = add2(shn, gh[b0 + 2 * HID]);
        }
        float2 ir = upk(sir), iz = upk(siz), inn = upk(sin);
        float2 hr = upk(shr), hz = upk(shz), hn = upk(shn);
        float br  = bih[u] + bhh[u];
        float bz  = bih[HID + u] + bhh[HID + u];
        float bin = bih[2 * HID + u];
        float bhn = bhh[2 * HID + u];
        float2 h = upk(hs[p * HID + u]);
        float rx = sigmf(ir.x + hr.x + br);
        float ry = sigmf(ir.y + hr.y + br);
        float zx = sigmf(iz.x + hz.x + bz);
        float zy = sigmf(iz.y + hz.y + bz);
        float nx = tanh_f(inn.x + bin + rx * (hn.x + bhn));
        float ny = tanh_f(inn.y + bin + ry * (hn.y + bhn));
        float ox = (1.0f - zx) * nx + zx * h.x;
        float oy = (1.0f - zy) * ny + zy * h.y;
        hs[p * HID + u] = pk2(ox, oy);
    }
}

// Decoder cell-0 gates: gi computed inline from pred (K=1 input GEMM folded).
__device__ __forceinline__ void gates_dec0(ull* hs, const ull* ghq,
                                           const ull* pred2,
                                           const float* __restrict__ dwih0,
                                           const float* bih, const float* bhh,
                                           int tid) {
    for (int i = tid; i < HID * NP; i += NT) {
        int u = i & (HID - 1);
        int p = i >> 7;
        int b0 = p * 384 + u;
        ull shr = 0, shz = 0, shn = 0;
#pragma unroll
        for (int s = 0; s < 4; s++) {
            const ull* gh = ghq + s * GBUF;
            shr = add2(shr, gh[b0]);
            shz = add2(shz, gh[b0 + HID]);
            shn = add2(shn, gh[b0 + 2 * HID]);
        }
        float2 hr = upk(shr), hz = upk(shz), hn = upk(shn);
        float2 pr = upk(pred2[p]);
        float wr = __ldg(&dwih0[u]);
        float wz = __ldg(&dwih0[HID + u]);
        float wn = __ldg(&dwih0[2 * HID + u]);
        float br  = bih[u] + bhh[u];
        float bz  = bih[HID + u] + bhh[HID + u];
        float bin = bih[2 * HID + u];
        float bhn = bhh[2 * HID + u];
        float2 h = upk(hs[p * HID + u]);
        float rx = sigmf(pr.x * wr + hr.x + br);
        float ry = sigmf(pr.y * wr + hr.y + br);
        float zx = sigmf(pr.x * wz + hz.x + bz);
        float zy = sigmf(pr.y * wz + hz.y + bz);
        float nx = tanh_f(pr.x * wn + bin + rx * (hn.x + bhn));
        float ny = tanh_f(pr.y * wn + bin + ry * (hn.y + bhn));
        float ox = (1.0f - zx) * nx + zx * h.x;
        float oy = (1.0f - zy) * ny + zy * h.y;
        hs[p * HID + u] = pk2(ox, oy);
    }
}

// ------------------------- fused weight transform ---------------------------
__global__ void tr_all(const float* __restrict__ w0, const float* __restrict__ w1,
                       const float* __restrict__ w2, const float* __restrict__ w3,
                       const float* __restrict__ w4, const float* __restrict__ w5,
                       const float* __restrict__ w6, const float* __restrict__ w7) {
    int i = blockIdx.x * blockDim.x + threadIdx.x;
    const int n0 = NFEAT * 384;
    const int nH = HID * 384;
    const int n7 = HID * 64;
    int seg, off;
    if (i < n0) { seg = 0; off = i; }
    else if (i < n0 + 6 * nH) { seg = 1 + (i - n0) / nH; off = (i - n0) % nH; }
    else if (i < n0 + 6 * nH + n7) { seg = 7; off = i - n0 - 6 * nH; }
    else return;

    const float* src = seg == 0 ? w0 : seg == 1 ? w1 : seg == 2 ? w2
                     : seg == 3 ? w3 : seg == 4 ? w4 : seg == 5 ? w5
                     : seg == 6 ? w6 : w7;
    float* dst = seg == 0 ? g_We0i : seg == 1 ? g_We0h : seg == 2 ? g_We1i
               : seg == 3 ? g_We1h : seg == 4 ? g_Wd0h : seg == 5 ? g_Wd1i
               : seg == 6 ? g_Wd1h : g_Wfc1;
    int K = seg == 0 ? NFEAT : HID;
    int J = seg == 7 ? 64 : 384;
    int j = off / K;
    int k = off % K;
    float v = src[off];
    if (seg == 7)
        dst[(k >> 1) * (2 * J) + 2 * j + (k & 1)] = v;
    else
        dst[(k >> 2) * (4 * J) + 4 * j + (k & 3)] = v;
}

// ------------------------- shared memory layout (ull units) -----------------
//   h0s 896 | h1s 896 | xs 112 | gi_q 4*2688 | gh_q 4*2688 | fch 448 | pred2 8
//   sb 8*384 f32 (1536) | sfcb1+sw2 (64)
#define SM_ULL (896 + 896 + 112 + 4*GBUF + 4*GBUF + 448 + 8 + 1536 + 64)
#define SMEM_BYTES (SM_ULL * 8)   // 203,712 B

__global__ void __launch_bounds__(NT) gru_main(
    const float* __restrict__ x,
    const float* __restrict__ be_ih0, const float* __restrict__ be_hh0,
    const float* __restrict__ be_ih1, const float* __restrict__ be_hh1,
    const float* __restrict__ dwih0,
    const float* __restrict__ bd_ih0, const float* __restrict__ bd_hh0,
    const float* __restrict__ bd_ih1, const float* __restrict__ bd_hh1,
    const float* __restrict__ fcb1, const float* __restrict__ fcw2,
    const float* __restrict__ fcb2,
    float* __restrict__ out) {
    extern __shared__ ull sm[];
    ull* h0s  = sm;                    // 896
    ull* h1s  = h0s + 896;             // 896
    ull* xs   = h1s + 896;             // 112
    ull* gi_q = xs + 112;              // 4*2688
    ull* gh_q = gi_q + 4 * GBUF;       // 4*2688
    ull* fch   = gh_q + 4 * GBUF;      // 448
    ull* pred2 = fch + NP * 64;        // 8
    float* sb    = reinterpret_cast<float*>(pred2 + 8);
    float* sfcb1 = sb + 8 * 384;
    float* sw2   = sfcb1 + 64;

    const int tid = threadIdx.x;
    const int q   = tid / 192;         // warp-uniform K-quarter
    const int jc  = tid % 192;         // lane-consecutive column base
    const int rowbase = blockIdx.x * NROW;
    ull* giW = gi_q + q * GBUF;
    ull* ghW = gh_q + q * GBUF;

    // init
    for (int i = tid; i < 2 * 896; i += NT) h0s[i] = 0ull;
    if (tid < 384) {
        const float* bsrc[8] = {be_ih0, be_hh0, be_ih1, be_hh1,
                                bd_ih0, bd_hh0, bd_ih1, bd_hh1};
#pragma unroll
        for (int a = 0; a < 8; a++) sb[a * 384 + tid] = bsrc[a][tid];
    }
    if (tid < 64) { sfcb1[tid] = fcb1[tid]; sw2[tid] = fcw2[tid]; }
    if (tid < 8) pred2[tid] = 0ull;
    __syncthreads();

    // =============================== encoder ===============================
    for (int t = 0; t < TIN; t++) {
        for (int i = tid; i < NP * NFEAT; i += NT) {
            int p = i >> 4, c = i & 15;
            int ra = rowbase + 2 * p;
            int rb = ra + 1;
            if (ra > BATCH - 1) ra = BATCH - 1;
            if (rb > BATCH - 1) rb = BATCH - 1;
            float a = x[(size_t)ra * TIN * NFEAT + (size_t)t * NFEAT + c];
            float b = x[(size_t)rb * TIN * NFEAT + (size_t)t * NFEAT + c];
            xs[p * NFEAT + c] = pk2(a, b);
        }
        __syncthreads();

        // layer 0
        gemm2q<NFEAT>(g_We0i, xs, giW, jc, q);
        gemm2q<HID>(g_We0h, h0s, ghW, jc, q);
        __syncthreads();
        gates4(h0s, gi_q, gh_q, sb + 0 * 384, sb + 1 * 384, tid);
        __syncthreads();

        // layer 1 (input = new h0)
        gemm2q<HID>(g_We1i, h0s, giW, jc, q);
        gemm2q<HID>(g_We1h, h1s, ghW, jc, q);
        __syncthreads();
        gates4(h1s, gi_q, gh_q, sb + 2 * 384, sb + 3 * 384, tid);
        __syncthreads();
    }

    // =============================== decoder ===============================
    const float b2 = __ldg(fcb2);

    for (int t = 0; t < TOUT; t++) {
        // cell 0: hh GEMM; K=1 input GEMM folded into gates_dec0
        gemm2q<HID>(g_Wd0h, h0s, ghW, jc, q);
        __syncthreads();
        gates_dec0(h0s, gh_q, pred2, dwih0, sb + 4 * 384, sb + 5 * 384, tid);
        __syncthreads();

        // cell 1 (input = new h0)
        gemm2q<HID>(g_Wd1i, h0s, giW, jc, q);
        gemm2q<HID>(g_Wd1h, h1s, ghW, jc, q);
        __syncthreads();
        gates4(h1s, gi_q, gh_q, sb + 6 * 384, sb + 7 * 384, tid);
        __syncthreads();

        // fc1: 64 cols x NP pairs, K=128, relu
        if (tid < 64 * NP) {
            int c = tid & 63, p = tid >> 6;
            ull a0 = 0ull, a1 = 0ull;
            const float2* W = reinterpret_cast<const float2*>(g_Wfc1);
#pragma unroll 8
            for (int k2 = 0; k2 < HID / 2; k2++) {
                float2 w = __ldg(&W[k2 * 64 + c]);
                ulonglong2 hv =
                    *reinterpret_cast<const ulonglong2*>(&h1s[p * HID + 2 * k2]);
                a0 = ffma2(hv.x, pk2(w.x, w.x), a0);
                a1 = ffma2(hv.y, pk2(w.y, w.y), a1);
            }
            float2 s0 = upk(a0), s1 = upk(a1);
            float vx = fmaxf(s0.x + s1.x + sfcb1[c], 0.0f);
            float vy = fmaxf(s0.y + s1.y + sfcb1[c], 0.0f);
            fch[p * 64 + c] = pk2(vx, vy);
        }
        __syncthreads();

        // fc2 + writeback + feedback: warp p handles pair p
        if (tid < 32 * NP) {
            int p = tid >> 5, l = tid & 31;
            ull a = ffma2(fch[p * 64 + 2 * l], pk2(sw2[2 * l], sw2[2 * l]), 0ull);
            a = ffma2(fch[p * 64 + 2 * l + 1],
                      pk2(sw2[2 * l + 1], sw2[2 * l + 1]), a);
            float2 s = upk(a);
#pragma unroll
            for (int o = 16; o > 0; o >>= 1) {
                s.x += __shfl_down_sync(0xffffffffu, s.x, o);
                s.y += __shfl_down_sync(0xffffffffu, s.y, o);
            }
            if (l == 0) {
                float px = fmaxf(s.x + b2, 0.0f);
                float py = fmaxf(s.y + b2, 0.0f);
                pred2[p] = pk2(px, py);
                int ra = rowbase + 2 * p;
                if (ra < BATCH) out[(size_t)ra * TOUT + t] = px;
                if (ra + 1 < BATCH) out[(size_t)(ra + 1) * TOUT + t] = py;
            }
        }
        __syncthreads();
    }
}

// ---------------------------------------------------------------------------
extern "C" void kernel_launch(void* const* d_in, const int* in_sizes, int n_in,
                              void* d_out, int out_size) {
    (void)in_sizes; (void)n_in; (void)out_size;
    const float* x     = (const float*)d_in[0];
    const float* eWih0 = (const float*)d_in[1];
    const float* eWhh0 = (const float*)d_in[2];
    const float* ebih0 = (const float*)d_in[3];
    const float* ebhh0 = (const float*)d_in[4];
    const float* eWih1 = (const float*)d_in[5];
    const float* eWhh1 = (const float*)d_in[6];
    const float* ebih1 = (const float*)d_in[7];
    const float* ebhh1 = (const float*)d_in[8];
    const float* dWih0 = (const float*)d_in[9];
    const float* dWhh0 = (const float*)d_in[10];
    const float* dbih0 = (const float*)d_in[11];
    const float* dbhh0 = (const float*)d_in[12];
    const float* dWih1 = (const float*)d_in[13];
    const float* dWhh1 = (const float*)d_in[14];
    const float* dbih1 = (const float*)d_in[15];
    const float* dbhh1 = (const float*)d_in[16];
    const float* fcW1  = (const float*)d_in[17];
    const float* fcb1  = (const float*)d_in[18];
    const float* fcW2  = (const float*)d_in[19];
    const float* fcb2  = (const float*)d_in[20];
    float* out = (float*)d_out;

    cudaFuncSetAttribute(gru_main, cudaFuncAttributeMaxDynamicSharedMemorySize,
                         (int)SMEM_BYTES);

    {
        int total = NFEAT * 384 + 6 * HID * 384 + HID * 64;
        int thr = 256;
        tr_all<<<(total + thr - 1) / thr, thr>>>(eWih0, eWhh0, eWih1, eWhh1,
                                                 dWhh0, dWih1, dWhh1, fcW1);
    }

    gru_main<<<NBLK, NT, SMEM_BYTES>>>(x,
                                       ebih0, ebhh0, ebih1, ebhh1,
                                       dWih0,
                                       dbih0, dbhh0, dbih1, dbhh1,
                                       fcb1, fcW2, fcb2,
                                       out);
}

// round 8
// speedup vs baseline: 1.0061x; 1.0061x over previous
#include <cuda_runtime.h>
#include <cstdint>

// ---------------------------------------------------------------------------
// GRUSeq2Seq on GB300 (sm_103a) — round 8
// 147 persistent CTAs x 14 batch rows (7 f32x2 pairs). NT=512:
//   tid = q*128 + jc   (q = warp-uniform K-quarter, jc = tid&127)
// Thread computes 3 gate columns (jc, +128, +256) x 7 row-pairs over its
// K-quarter -> 84 FFMA2 per 40 L1-wavefronts (fma-bound by design).
// Zero weight-load redundancy. K-partials in 4 smem buffers, combined in the
// gates phase. fp32 via fma.rn.f32x2.
// ---------------------------------------------------------------------------

#define HID   128
#define NFEAT 16
#define TIN   336
#define TOUT  168
#define BATCH 2048
#define NP    7
#define NROW  (2*NP)
#define NT    512
#define NBLK  147
#define GBUF  2688        // ull per partial gate buffer (NP*384)

typedef unsigned long long ull;

// ------------------------- transposed weight scratch -----------------------
__device__ float g_We0i[NFEAT * 384];  // float4 layout [k/4][384][4]
__device__ float g_We0h[HID * 384];
__device__ float g_We1i[HID * 384];
__device__ float g_We1h[HID * 384];
__device__ float g_Wd0h[HID * 384];
__device__ float g_Wd1i[HID * 384];
__device__ float g_Wd1h[HID * 384];
__device__ float g_Wfc1[HID * 64];     // pair layout [k/2][64][2]

// ------------------------- packed f32x2 helpers ----------------------------
__device__ __forceinline__ ull pk2(float lo, float hi) {
    ull r;
    asm("mov.b64 %0, {%1, %2};" : "=l"(r) : "f"(lo), "f"(hi));
    return r;
}
__device__ __forceinline__ float2 upk(ull v) {
    float a, b;
    asm("mov.b64 {%0, %1}, %2;" : "=f"(a), "=f"(b) : "l"(v));
    return make_float2(a, b);
}
__device__ __forceinline__ ull ffma2(ull a, ull b, ull c) {
    ull d;
    asm("fma.rn.f32x2 %0, %1, %2, %3;" : "=l"(d) : "l"(a), "l"(b), "l"(c));
    return d;
}
__device__ __forceinline__ ull add2(ull a, ull b) {
    ull d;
    asm("add.rn.f32x2 %0, %1, %2;" : "=l"(d) : "l"(a), "l"(b));
    return d;
}

__device__ __forceinline__ float sigmf(float v) {
    return 1.0f / (1.0f + __expf(-v));
}
__device__ __forceinline__ float tanh_f(float v) {
    float e = __expf(-2.0f * fabsf(v));
    float t = (1.0f - e) / (1.0f + e);
    return copysignf(t, v);
}

// ------------------------- quarter-K triple-column GEMM ---------------------
// Thread computes columns jc, jc+128, jc+256 for all NP row-pairs over
// K-quarter q. Partial sums stored to dst (the q-th partial buffer). h reads
// are warp-uniform (q, k4, p identical across lanes) -> LDS broadcast.
template <int K>
__device__ __forceinline__ void gemm3q(const float* __restrict__ Wf,
                                       const ull* __restrict__ hs,
                                       ull* __restrict__ dst,
                                       int jc, int q) {
    const float4* W4 = reinterpret_cast<const float4*>(Wf);
    constexpr int QG = K / 16;          // float4 groups per K-quarter
    const int k4b = q * QG;
    ull a0[NP], a1[NP], a2[NP];
#pragma unroll
    for (int p = 0; p < NP; p++) { a0[p] = 0ull; a1[p] = 0ull; a2[p] = 0ull; }

#pragma unroll 2
    for (int i = 0; i < QG; i++) {
        const int k4 = k4b + i;
        const float4* wrow = &W4[k4 * 384 + jc];
        float4 wA = __ldg(wrow);
        float4 wB = __ldg(wrow + 128);
        float4 wC = __ldg(wrow + 256);
        ull wa0 = pk2(wA.x, wA.x), wa1 = pk2(wA.y, wA.y);
        ull wa2 = pk2(wA.z, wA.z), wa3 = pk2(wA.w, wA.w);
        ull wb0 = pk2(wB.x, wB.x), wb1 = pk2(wB.y, wB.y);
        ull wb2 = pk2(wB.z, wB.z), wb3 = pk2(wB.w, wB.w);
        ull wc0 = pk2(wC.x, wC.x), wc1 = pk2(wC.y, wC.y);
        ull wc2 = pk2(wC.z, wC.z), wc3 = pk2(wC.w, wC.w);
#pragma unroll
        for (int p = 0; p < NP; p++) {
            const ull* hp = &hs[p * K + 4 * k4];
            ulonglong2 h01 = *reinterpret_cast<const ulonglong2*>(hp);
            ulonglong2 h23 = *reinterpret_cast<const ulonglong2*>(hp + 2);
            a0[p] = ffma2(h01.x, wa0, a0[p]);
            a1[p] = ffma2(h01.x, wb0, a1[p]);
            a2[p] = ffma2(h01.x, wc0, a2[p]);
            a0[p] = ffma2(h01.y, wa1, a0[p]);
            a1[p] = ffma2(h01.y, wb1, a1[p]);
            a2[p] = ffma2(h01.y, wc1, a2[p]);
            a0[p] = ffma2(h23.x, wa2, a0[p]);
            a1[p] = ffma2(h23.x, wb2, a1[p]);
            a2[p] = ffma2(h23.x, wc2, a2[p]);
            a0[p] = ffma2(h23.y, wa3, a0[p]);
            a1[p] = ffma2(h23.y, wb3, a1[p]);
            a2[p] = ffma2(h23.y, wc3, a2[p]);
        }
    }
#pragma unroll
    for (int p = 0; p < NP; p++) {
        dst[p * 384 + jc]       = a0[p];
        dst[p * 384 + jc + 128] = a1[p];
        dst[p * 384 + jc + 256] = a2[p];
    }
}

// ------------------------- GRU gate phase (4-way combine) -------------------
__device__ __forceinline__ void gates4(ull* hs,
                                       const ull* giq, const ull* ghq,
                                       const float* bih, const float* bhh,
                                       int tid) {
    for (int i = tid; i < HID * NP; i += NT) {
        int u = i & (HID - 1);
        int p = i >> 7;
        int b0 = p * 384 + u;
        ull sir = 0, siz = 0, sin = 0, shr = 0, shz = 0, shn = 0;
#pragma unroll
        for (int s = 0; s < 4; s++) {
            const ull* gi = giq + s * GBUF;
            const ull* gh = ghq + s * GBUF;
            sir = add2(sir, gi[b0]);
            siz = add2(siz, gi[b0 + HID]);
            sin = add2(sin, gi[b0 + 2 * HID]);
            shr = add2(shr, gh[b0]);
            shz = add2(shz, gh[b0 + HID]);
            shn = add2(shn, gh[b0 + 2 * HID]);
        }
        float2 ir = upk(sir), iz = upk(siz), inn = upk(sin);
        float2 hr = upk(shr), hz = upk(shz), hn = upk(shn);
        float br  = bih[u] + bhh[u];
        float bz  = bih[HID + u] + bhh[HID + u];
        float bin = bih[2 * HID + u];
        float bhn = bhh[2 * HID + u];
        float2 h = upk(hs[p * HID + u]);
        float rx = sigmf(ir.x + hr.x + br);
        float ry = sigmf(ir.y + hr.y + br);
        float zx = sigmf(iz.x + hz.x + bz);
        float zy = sigmf(iz.y + hz.y + bz);
        float nx = tanh_f(inn.x + bin + rx * (hn.x + bhn));
        float ny = tanh_f(inn.y + bin + ry * (hn.y + bhn));
        float ox = (1.0f - zx) * nx + zx * h.x;
        float oy = (1.0f - zy) * ny + zy * h.y;
        hs[p * HID + u] = pk2(ox, oy);
    }
}

// Decoder cell-0 gates: gi computed inline from pred (K=1 input GEMM folded).
__device__ __forceinline__ void gates_dec0(ull* hs, const ull* ghq,
                                           const ull* pred2,
                                           const float* __restrict__ dwih0,
                                           const float* bih, const float* bhh,
                                           int tid) {
    for (int i = tid; i < HID * NP; i += NT) {
        int u = i & (HID - 1);
        int p = i >> 7;
        int b0 = p * 384 + u;
        ull shr = 0, shz = 0, shn = 0;
#pragma unroll
        for (int s = 0; s < 4; s++) {
            const ull* gh = ghq + s * GBUF;
            shr = add2(shr, gh[b0]);
            shz = add2(shz, gh[b0 + HID]);
            shn = add2(shn, gh[b0 + 2 * HID]);
        }
        float2 hr = upk(shr), hz = upk(shz), hn = upk(shn);
        float2 pr = upk(pred2[p]);
        float wr = __ldg(&dwih0[u]);
        float wz = __ldg(&dwih0[HID + u]);
        float wn = __ldg(&dwih0[2 * HID + u]);
        float br  = bih[u] + bhh[u];
        float bz  = bih[HID + u] + bhh[HID + u];
        float bin = bih[2 * HID + u];
        float bhn = bhh[2 * HID + u];
        float2 h = upk(hs[p * HID + u]);
        float rx = sigmf(pr.x * wr + hr.x + br);
        float ry = sigmf(pr.y * wr + hr.y + br);
        float zx = sigmf(pr.x * wz + hz.x + bz);
        float zy = sigmf(pr.y * wz + hz.y + bz);
        float nx = tanh_f(pr.x * wn + bin + rx * (hn.x + bhn));
        float ny = tanh_f(pr.y * wn + bin + ry * (hn.y + bhn));
        float ox = (1.0f - zx) * nx + zx * h.x;
        float oy = (1.0f - zy) * ny + zy * h.y;
        hs[p * HID + u] = pk2(ox, oy);
    }
}

// ------------------------- fused weight transform ---------------------------
__global__ void tr_all(const float* __restrict__ w0, const float* __restrict__ w1,
                       const float* __restrict__ w2, const float* __restrict__ w3,
                       const float* __restrict__ w4, const float* __restrict__ w5,
                       const float* __restrict__ w6, const float* __restrict__ w7) {
    int i = blockIdx.x * blockDim.x + threadIdx.x;
    const int n0 = NFEAT * 384;
    const int nH = HID * 384;
    const int n7 = HID * 64;
    int seg, off;
    if (i < n0) { seg = 0; off = i; }
    else if (i < n0 + 6 * nH) { seg = 1 + (i - n0) / nH; off = (i - n0) % nH; }
    else if (i < n0 + 6 * nH + n7) { seg = 7; off = i - n0 - 6 * nH; }
    else return;

    const float* src = seg == 0 ? w0 : seg == 1 ? w1 : seg == 2 ? w2
                     : seg == 3 ? w3 : seg == 4 ? w4 : seg == 5 ? w5
                     : seg == 6 ? w6 : w7;
    float* dst = seg == 0 ? g_We0i : seg == 1 ? g_We0h : seg == 2 ? g_We1i
               : seg == 3 ? g_We1h : seg == 4 ? g_Wd0h : seg == 5 ? g_Wd1i
               : seg == 6 ? g_Wd1h : g_Wfc1;
    int K = seg == 0 ? NFEAT : HID;
    int J = seg == 7 ? 64 : 384;
    int j = off / K;
    int k = off % K;
    float v = src[off];
    if (seg == 7)
        dst[(k >> 1) * (2 * J) + 2 * j + (k & 1)] = v;
    else
        dst[(k >> 2) * (4 * J) + 4 * j + (k & 3)] = v;
}

// ------------------------- shared memory layout (ull units) -----------------
//   h0s 896 | h1s 896 | xs 112 | gi_q 4*2688 | gh_q 4*2688 | fch 448 | pred2 8
//   sb 8*384 f32 (1536) | sfcb1+sw2 (64)
#define SM_ULL (896 + 896 + 112 + 4*GBUF + 4*GBUF + 448 + 8 + 1536 + 64)
#define SMEM_BYTES (SM_ULL * 8)   // 203,712 B

__global__ void __launch_bounds__(NT) gru_main(
    const float* __restrict__ x,
    const float* __restrict__ be_ih0, const float* __restrict__ be_hh0,
    const float* __restrict__ be_ih1, const float* __restrict__ be_hh1,
    const float* __restrict__ dwih0,
    const float* __restrict__ bd_ih0, const float* __restrict__ bd_hh0,
    const float* __restrict__ bd_ih1, const float* __restrict__ bd_hh1,
    const float* __restrict__ fcb1, const float* __restrict__ fcw2,
    const float* __restrict__ fcb2,
    float* __restrict__ out) {
    extern __shared__ ull sm[];
    ull* h0s  = sm;                    // 896
    ull* h1s  = h0s + 896;             // 896
    ull* xs   = h1s + 896;             // 112
    ull* gi_q = xs + 112;              // 4*2688
    ull* gh_q = gi_q + 4 * GBUF;       // 4*2688
    ull* fch   = gh_q + 4 * GBUF;      // 448
    ull* pred2 = fch + NP * 64;        // 8
    float* sb    = reinterpret_cast<float*>(pred2 + 8);
    float* sfcb1 = sb + 8 * 384;
    float* sw2   = sfcb1 + 64;

    const int tid = threadIdx.x;
    const int q   = tid >> 7;          // warp-uniform K-quarter
    const int jc  = tid & 127;         // lane-consecutive column base
    const int rowbase = blockIdx.x * NROW;
    ull* giW = gi_q + q * GBUF;
    ull* ghW = gh_q + q * GBUF;

    // init
    for (int i = tid; i < 2 * 896; i += NT) h0s[i] = 0ull;
    if (tid < 384) {
        const float* bsrc[8] = {be_ih0, be_hh0, be_ih1, be_hh1,
                                bd_ih0, bd_hh0, bd_ih1, bd_hh1};
#pragma unroll
        for (int a = 0; a < 8; a++) sb[a * 384 + tid] = bsrc[a][tid];
    }
    if (tid < 64) { sfcb1[tid] = fcb1[tid]; sw2[tid] = fcw2[tid]; }
    if (tid < 8) pred2[tid] = 0ull;
    __syncthreads();

    // =============================== encoder ===============================
    for (int t = 0; t < TIN; t++) {
        for (int i = tid; i < NP * NFEAT; i += NT) {
            int p = i >> 4, c = i & 15;
            int ra = rowbase + 2 * p;
            int rb = ra + 1;
            if (ra > BATCH - 1) ra = BATCH - 1;
            if (rb > BATCH - 1) rb = BATCH - 1;
            float a = x[(size_t)ra * TIN * NFEAT + (size_t)t * NFEAT + c];
            float b = x[(size_t)rb * TIN * NFEAT + (size_t)t * NFEAT + c];
            xs[p * NFEAT + c] = pk2(a, b);
        }
        __syncthreads();

        // layer 0
        gemm3q<NFEAT>(g_We0i, xs, giW, jc, q);
        gemm3q<HID>(g_We0h, h0s, ghW, jc, q);
        __syncthreads();
        gates4(h0s, gi_q, gh_q, sb + 0 * 384, sb + 1 * 384, tid);
        __syncthreads();

        // layer 1 (input = new h0)
        gemm3q<HID>(g_We1i, h0s, giW, jc, q);
        gemm3q<HID>(g_We1h, h1s, ghW, jc, q);
        __syncthreads();
        gates4(h1s, gi_q, gh_q, sb + 2 * 384, sb + 3 * 384, tid);
        __syncthreads();
    }

    // =============================== decoder ===============================
    const float b2 = __ldg(fcb2);

    for (int t = 0; t < TOUT; t++) {
        // cell 0: hh GEMM; K=1 input GEMM folded into gates_dec0
        gemm3q<HID>(g_Wd0h, h0s, ghW, jc, q);
        __syncthreads();
        gates_dec0(h0s, gh_q, pred2, dwih0, sb + 4 * 384, sb + 5 * 384, tid);
        __syncthreads();

        // cell 1 (input = new h0)
        gemm3q<HID>(g_Wd1i, h0s, giW, jc, q);
        gemm3q<HID>(g_Wd1h, h1s, ghW, jc, q);
        __syncthreads();
        gates4(h1s, gi_q, gh_q, sb + 6 * 384, sb + 7 * 384, tid);
        __syncthreads();

        // fc1: 64 cols x NP pairs, K=128, relu
        if (tid < 64 * NP) {
            int c = tid & 63, p = tid >> 6;
            ull a0 = 0ull, a1 = 0ull;
            const float2* W = reinterpret_cast<const float2*>(g_Wfc1);
#pragma unroll 8
            for (int k2 = 0; k2 < HID / 2; k2++) {
                float2 w = __ldg(&W[k2 * 64 + c]);
                ulonglong2 hv =
                    *reinterpret_cast<const ulonglong2*>(&h1s[p * HID + 2 * k2]);
                a0 = ffma2(hv.x, pk2(w.x, w.x), a0);
                a1 = ffma2(hv.y, pk2(w.y, w.y), a1);
            }
            float2 s0 = upk(a0), s1 = upk(a1);
            float vx = fmaxf(s0.x + s1.x + sfcb1[c], 0.0f);
            float vy = fmaxf(s0.y + s1.y + sfcb1[c], 0.0f);
            fch[p * 64 + c] = pk2(vx, vy);
        }
        __syncthreads();

        // fc2 + writeback + feedback: warp p handles pair p
        if (tid < 32 * NP) {
            int p = tid >> 5, l = tid & 31;
            ull a = ffma2(fch[p * 64 + 2 * l], pk2(sw2[2 * l], sw2[2 * l]), 0ull);
            a = ffma2(fch[p * 64 + 2 * l + 1],
                      pk2(sw2[2 * l + 1], sw2[2 * l + 1]), a);
            float2 s = upk(a);
#pragma unroll
            for (int o = 16; o > 0; o >>= 1) {
                s.x += __shfl_down_sync(0xffffffffu, s.x, o);
                s.y += __shfl_down_sync(0xffffffffu, s.y, o);
            }
            if (l == 0) {
                float px = fmaxf(s.x + b2, 0.0f);
                float py = fmaxf(s.y + b2, 0.0f);
                pred2[p] = pk2(px, py);
                int ra = rowbase + 2 * p;
                if (ra < BATCH) out[(size_t)ra * TOUT + t] = px;
                if (ra + 1 < BATCH) out[(size_t)(ra + 1) * TOUT + t] = py;
            }
        }
        __syncthreads();
    }
}

// ---------------------------------------------------------------------------
extern "C" void kernel_launch(void* const* d_in, const int* in_sizes, int n_in,
                              void* d_out, int out_size) {
    (void)in_sizes; (void)n_in; (void)out_size;
    const float* x     = (const float*)d_in[0];
    const float* eWih0 = (const float*)d_in[1];
    const float* eWhh0 = (const float*)d_in[2];
    const float* ebih0 = (const float*)d_in[3];
    const float* ebhh0 = (const float*)d_in[4];
    const float* eWih1 = (const float*)d_in[5];
    const float* eWhh1 = (const float*)d_in[6];
    const float* ebih1 = (const float*)d_in[7];
    const float* ebhh1 = (const float*)d_in[8];
    const float* dWih0 = (const float*)d_in[9];
    const float* dWhh0 = (const float*)d_in[10];
    const float* dbih0 = (const float*)d_in[11];
    const float* dbhh0 = (const float*)d_in[12];
    const float* dWih1 = (const float*)d_in[13];
    const float* dWhh1 = (const float*)d_in[14];
    const float* dbih1 = (const float*)d_in[15];
    const float* dbhh1 = (const float*)d_in[16];
    const float* fcW1  = (const float*)d_in[17];
    const float* fcb1  = (const float*)d_in[18];
    const float* fcW2  = (const float*)d_in[19];
    const float* fcb2  = (const float*)d_in[20];
    float* out = (float*)d_out;

    cudaFuncSetAttribute(gru_main, cudaFuncAttributeMaxDynamicSharedMemorySize,
                         (int)SMEM_BYTES);

    {
        int total = NFEAT * 384 + 6 * HID * 384 + HID * 64;
        int thr = 256;
        tr_all<<<(total + thr - 1) / thr, thr>>>(eWih0, eWhh0, eWih1, eWhh1,
                                                 dWhh0, dWih1, dWhh1, fcW1);
    }

    gru_main<<<NBLK, NT, SMEM_BYTES>>>(x,
                                       ebih0, ebhh0, ebih1, ebhh1,
                                       dWih0,
                                       dbih0, dbhh0, dbih1, dbhh1,
                                       fcb1, fcW2, fcb2,
                                       out);
}